// round 2
// baseline (speedup 1.0000x reference)
#include <cuda_runtime.h>
#include <math.h>

#define NROWS 65536
#define IN_DIM 1024
#define H1D 512
#define H2D 256
#define LATD 64
#define NCODE 1024
#define COMMIT_BETA 0.25

// -------- scratch (device globals: allocation-free per harness rules) --------
__device__ float g_h1[(size_t)NROWS * H1D];   // 134 MB  (h1, then d2)
__device__ float g_h2[(size_t)NROWS * H2D];   // 67 MB   (h2, then d1)
__device__ float g_zq[(size_t)NROWS * LATD];  // 17 MB
__device__ float g_esq[NCODE];
__device__ double g_loss;

// ============================================================================
// Double-buffered SGEMM: C = act(A[M,K] @ B[K,N] + bias), all row-major fp32.
// ACT: 0 = none, 1 = relu, 2 = tanh
// ============================================================================
template<int BM,int BN,int BK,int TM,int TN,int ACT>
__global__ __launch_bounds__((BM/TM)*(BN/TN), 2)
void gemm_bias_act(const float* __restrict__ A, const float* __restrict__ B,
                   const float* __restrict__ bias, float* __restrict__ C,
                   int M, int N, int K)
{
    constexpr int NT = (BM/TM)*(BN/TN);
    constexpr int LA = (BM*BK)/(NT*4);
    constexpr int LB = (BK*BN)/(NT*4);

    __shared__ __align__(16) float As[2][BK][BM];
    __shared__ __align__(16) float Bs[2][BK][BN];

    const int tid = threadIdx.x;
    const int m0 = blockIdx.x * BM;
    const int n0 = blockIdx.y * BN;
    const int tx = tid % (BN/TN);
    const int ty = tid / (BN/TN);

    float acc[TM][TN];
    #pragma unroll
    for (int i = 0; i < TM; i++)
        #pragma unroll
        for (int j = 0; j < TN; j++) acc[i][j] = 0.f;

    float4 ra[LA], rb[LB];

    // ---- prologue: load tile 0 into buffer 0 ----
    #pragma unroll
    for (int j = 0; j < LA; j++) {
        int i = (tid + j*NT) * 4;
        int r = i / BK, c = i % BK;
        ra[j] = *reinterpret_cast<const float4*>(&A[(size_t)(m0 + r)*K + c]);
    }
    #pragma unroll
    for (int j = 0; j < LB; j++) {
        int i = (tid + j*NT) * 4;
        int r = i / BN, c = i % BN;
        rb[j] = *reinterpret_cast<const float4*>(&B[(size_t)r*N + n0 + c]);
    }
    #pragma unroll
    for (int j = 0; j < LA; j++) {
        int i = (tid + j*NT) * 4;
        int r = i / BK, c = i % BK;
        As[0][c+0][r] = ra[j].x; As[0][c+1][r] = ra[j].y;
        As[0][c+2][r] = ra[j].z; As[0][c+3][r] = ra[j].w;
    }
    #pragma unroll
    for (int j = 0; j < LB; j++) {
        int i = (tid + j*NT) * 4;
        int r = i / BN, c = i % BN;
        *reinterpret_cast<float4*>(&Bs[0][r][c]) = rb[j];
    }
    __syncthreads();

    const int ntiles = K / BK;
    #pragma unroll 1
    for (int t = 1; t < ntiles; t++) {
        const int k0 = t * BK;
        // prefetch next tile into registers
        #pragma unroll
        for (int j = 0; j < LA; j++) {
            int i = (tid + j*NT) * 4;
            int r = i / BK, c = i % BK;
            ra[j] = *reinterpret_cast<const float4*>(&A[(size_t)(m0 + r)*K + k0 + c]);
        }
        #pragma unroll
        for (int j = 0; j < LB; j++) {
            int i = (tid + j*NT) * 4;
            int r = i / BN, c = i % BN;
            rb[j] = *reinterpret_cast<const float4*>(&B[(size_t)(k0 + r)*N + n0 + c]);
        }
        // compute on current buffer
        const int cur = (t - 1) & 1;
        #pragma unroll
        for (int k = 0; k < BK; k++) {
            float a[TM], b[TN];
            #pragma unroll
            for (int i = 0; i < TM; i += 4) {
                float4 v = *reinterpret_cast<const float4*>(&As[cur][k][ty*TM + i]);
                a[i] = v.x; a[i+1] = v.y; a[i+2] = v.z; a[i+3] = v.w;
            }
            #pragma unroll
            for (int j = 0; j < TN; j += 4) {
                float4 v = *reinterpret_cast<const float4*>(&Bs[cur][k][tx*TN + j]);
                b[j] = v.x; b[j+1] = v.y; b[j+2] = v.z; b[j+3] = v.w;
            }
            #pragma unroll
            for (int i = 0; i < TM; i++)
                #pragma unroll
                for (int j = 0; j < TN; j++)
                    acc[i][j] = fmaf(a[i], b[j], acc[i][j]);
        }
        // store prefetched tile into next buffer (safe: prev sync ordered all reads)
        const int nxt = t & 1;
        #pragma unroll
        for (int j = 0; j < LA; j++) {
            int i = (tid + j*NT) * 4;
            int r = i / BK, c = i % BK;
            As[nxt][c+0][r] = ra[j].x; As[nxt][c+1][r] = ra[j].y;
            As[nxt][c+2][r] = ra[j].z; As[nxt][c+3][r] = ra[j].w;
        }
        #pragma unroll
        for (int j = 0; j < LB; j++) {
            int i = (tid + j*NT) * 4;
            int r = i / BN, c = i % BN;
            *reinterpret_cast<float4*>(&Bs[nxt][r][c]) = rb[j];
        }
        __syncthreads();
    }
    // last tile
    {
        const int cur = (ntiles - 1) & 1;
        #pragma unroll
        for (int k = 0; k < BK; k++) {
            float a[TM], b[TN];
            #pragma unroll
            for (int i = 0; i < TM; i += 4) {
                float4 v = *reinterpret_cast<const float4*>(&As[cur][k][ty*TM + i]);
                a[i] = v.x; a[i+1] = v.y; a[i+2] = v.z; a[i+3] = v.w;
            }
            #pragma unroll
            for (int j = 0; j < TN; j += 4) {
                float4 v = *reinterpret_cast<const float4*>(&Bs[cur][k][tx*TN + j]);
                b[j] = v.x; b[j+1] = v.y; b[j+2] = v.z; b[j+3] = v.w;
            }
            #pragma unroll
            for (int i = 0; i < TM; i++)
                #pragma unroll
                for (int j = 0; j < TN; j++)
                    acc[i][j] = fmaf(a[i], b[j], acc[i][j]);
        }
    }

    // ---- epilogue: bias + activation, vectorized stores ----
    float bv[TN];
    #pragma unroll
    for (int j = 0; j < TN; j++) bv[j] = bias[n0 + tx*TN + j];
    #pragma unroll
    for (int i = 0; i < TM; i++) {
        const int row = m0 + ty*TM + i;
        float* Cp = &C[(size_t)row*N + n0 + tx*TN];
        #pragma unroll
        for (int j = 0; j < TN; j += 4) {
            float vv[4];
            #pragma unroll
            for (int q = 0; q < 4; q++) {
                float u = acc[i][j+q] + bv[j+q];
                if (ACT == 1) u = fmaxf(u, 0.f);
                else if (ACT == 2) u = tanhf(u);
                vv[q] = u;
            }
            *reinterpret_cast<float4*>(&Cp[j]) = make_float4(vv[0], vv[1], vv[2], vv[3]);
        }
    }
}

// ============================================================================
// prep: codebook squared norms + zero the loss accumulator (runs every launch)
// sequential-order fp32 FMA to mirror the reference reduction rounding.
// ============================================================================
__global__ void prep_kernel(const float* __restrict__ cb)
{
    const int c = blockIdx.x * blockDim.x + threadIdx.x;
    if (c == 0) g_loss = 0.0;
    if (c < NCODE) {
        const float* p = &cb[(size_t)c * LATD];
        float s = 0.f;
        #pragma unroll
        for (int i = 0; i < LATD; i++) s = fmaf(p[i], p[i], s);
        g_esq[c] = s;
    }
}

// ============================================================================
// VQ: per-row argmin over 1024 codes (dim 64), gather z_q, commitment loss.
// CRITICAL: replicate the reference fp32 rounding of
//   dists = (z_sq - 2*(z.e)) + e_sq
// including the large-z_sq quantization, so near-tie rows resolve identically
// (strict < with ascending scan == jnp.argmin first-min tie-break).
// ============================================================================
__global__ __launch_bounds__(256)
void vq_kernel(const float* __restrict__ z, const float* __restrict__ cb,
               float* __restrict__ zq, float* __restrict__ idx_out)
{
    __shared__ __align__(16) float4 sc[128 * 16];   // 128 codes x 64 f32 = 32KB
    __shared__ float sesq[128];
    __shared__ float wsum[8];

    const int tid = threadIdx.x;
    const int row = blockIdx.x * 256 + tid;

    float4 zr[16];
    const float4* zp = reinterpret_cast<const float4*>(&z[(size_t)row * LATD]);
    #pragma unroll
    for (int i = 0; i < 16; i++) zr[i] = zp[i];

    // z_sq: sequential in-order fp32 FMA (matches reference reduction)
    float z_sq = 0.f;
    #pragma unroll
    for (int i = 0; i < 16; i++) {
        z_sq = fmaf(zr[i].x, zr[i].x, z_sq);
        z_sq = fmaf(zr[i].y, zr[i].y, z_sq);
        z_sq = fmaf(zr[i].z, zr[i].z, z_sq);
        z_sq = fmaf(zr[i].w, zr[i].w, z_sq);
    }

    float best = 3.4028235e38f;
    int bi = 0;
    for (int c0 = 0; c0 < NCODE; c0 += 128) {
        __syncthreads();
        const float4* cp = reinterpret_cast<const float4*>(&cb[(size_t)c0 * LATD]);
        #pragma unroll
        for (int j = 0; j < 8; j++) sc[tid + j*256] = cp[tid + j*256];
        if (tid < 128) sesq[tid] = g_esq[c0 + tid];
        __syncthreads();

        #pragma unroll 4
        for (int c = 0; c < 128; c++) {
            const float4* e = &sc[c * 16];
            float acc = 0.f;
            #pragma unroll
            for (int i = 0; i < 16; i++) {
                float4 v = e[i];
                acc = fmaf(zr[i].x, v.x, acc);
                acc = fmaf(zr[i].y, v.y, acc);
                acc = fmaf(zr[i].z, v.z, acc);
                acc = fmaf(zr[i].w, v.w, acc);
            }
            // reference association: (z_sq - 2*zc) + e_sq, all fp32 rounded
            float t = z_sq - 2.0f * acc;
            float d = t + sesq[c];
            if (d < best) { best = d; bi = c0 + c; }
        }
    }

    // gather z_q + per-row commitment sum
    const float4* ep = reinterpret_cast<const float4*>(&cb[(size_t)bi * LATD]);
    float4* qp = reinterpret_cast<float4*>(&zq[(size_t)row * LATD]);
    float ls = 0.f;
    #pragma unroll
    for (int i = 0; i < 16; i++) {
        float4 e = ep[i];
        qp[i] = e;
        float dx = e.x - zr[i].x, dy = e.y - zr[i].y;
        float dz = e.z - zr[i].z, dw = e.w - zr[i].w;
        ls += dx*dx + dy*dy + dz*dz + dw*dw;
    }
    idx_out[row] = (float)bi;

    // block reduction of loss -> double atomic (numerically stable)
    #pragma unroll
    for (int o = 16; o > 0; o >>= 1) ls += __shfl_down_sync(0xffffffffu, ls, o);
    if ((tid & 31) == 0) wsum[tid >> 5] = ls;
    __syncthreads();
    if (tid == 0) {
        float s = 0.f;
        #pragma unroll
        for (int i = 0; i < 8; i++) s += wsum[i];
        atomicAdd(&g_loss, (double)s);
    }
}

__global__ void fin_kernel(float* __restrict__ loss_out)
{
    loss_out[0] = (float)(COMMIT_BETA * g_loss / ((double)NROWS * LATD));
}

// ============================================================================
// launch
// ============================================================================
extern "C" void kernel_launch(void* const* d_in, const int* in_sizes, int n_in,
                              void* d_out, int out_size)
{
    const float* x   = (const float*)d_in[0];
    const float* We1 = (const float*)d_in[1];
    const float* be1 = (const float*)d_in[2];
    const float* We2 = (const float*)d_in[3];
    const float* be2 = (const float*)d_in[4];
    const float* We3 = (const float*)d_in[5];
    const float* be3 = (const float*)d_in[6];
    const float* cb  = (const float*)d_in[7];
    const float* Wd1 = (const float*)d_in[8];
    const float* bd1 = (const float*)d_in[9];
    const float* Wd2 = (const float*)d_in[10];
    const float* bd2 = (const float*)d_in[11];
    const float* Wd3 = (const float*)d_in[12];
    const float* bd3 = (const float*)d_in[13];

    float* out   = (float*)d_out;
    float* xrec  = out;                                  // [N, 1024]
    float* zout  = out + (size_t)NROWS * IN_DIM;         // [N, 64]
    float* idxo  = zout + (size_t)NROWS * LATD;          // [N]
    float* losso = idxo + NROWS;                         // [1]

    float *h1, *h2, *zq;
    cudaGetSymbolAddress((void**)&h1, g_h1);
    cudaGetSymbolAddress((void**)&h2, g_h2);
    cudaGetSymbolAddress((void**)&zq, g_zq);

    prep_kernel<<<4, 256>>>(cb);

    // encoder
    gemm_bias_act<128,128,8,8,8,1><<<dim3(NROWS/128, 4), 256>>>(x,  We1, be1, h1,   NROWS, 512,  1024);
    gemm_bias_act<128,128,8,8,8,1><<<dim3(NROWS/128, 2), 256>>>(h1, We2, be2, h2,   NROWS, 256,  512);
    gemm_bias_act<128, 64,16,8,4,0><<<dim3(NROWS/128, 1), 256>>>(h2, We3, be3, zout, NROWS, 64,   256);

    // vector quantization (reads z from d_out region)
    vq_kernel<<<NROWS/256, 256>>>(zout, cb, zq, idxo);

    // decoder (z_q_st forward value == z_q)
    gemm_bias_act<128,128,8,8,8,1><<<dim3(NROWS/128, 2), 256>>>(zq, Wd1, bd1, h2,   NROWS, 256,  64);
    gemm_bias_act<128,128,8,8,8,1><<<dim3(NROWS/128, 4), 256>>>(h2, Wd2, bd2, h1,   NROWS, 512,  256);
    gemm_bias_act<128,128,8,8,8,2><<<dim3(NROWS/128, 8), 256>>>(h1, Wd3, bd3, xrec, NROWS, 1024, 512);

    fin_kernel<<<1, 1>>>(losso);
}